// round 1
// baseline (speedup 1.0000x reference)
#include <cuda_runtime.h>

// Problem: y_pred [16,3,512,512] f32, y_true same. Output [B,C,4] = 192 f32.
// Only need sp=Σp, st=Σt, spt=Σpt per (b,c):
//   tp=spt, fp=sp-spt, fn=st-spt, tn=N-sp-st+spt.

constexpr int GROUPS = 48;               // B*C
constexpr int N_PER_GROUP = 512 * 512;   // 262144
constexpr int BLOCKS_PER_GROUP = 16;
constexpr int THREADS = 256;
constexpr int ELEMS_PER_BLOCK = N_PER_GROUP / BLOCKS_PER_GROUP;  // 16384
constexpr int VEC_PER_BLOCK = ELEMS_PER_BLOCK / 4;               // 4096 float4
constexpr int VEC_PER_THREAD = VEC_PER_BLOCK / THREADS;          // 16

// Stage-1 partials: [group][block][4] (sp, st, spt, pad)
__device__ float g_partials[GROUPS * BLOCKS_PER_GROUP * 4];

__global__ __launch_bounds__(THREADS, 8)
void cm_stage1(const float* __restrict__ p_in, const float* __restrict__ t_in) {
    const int group = blockIdx.x / BLOCKS_PER_GROUP;
    const int blk   = blockIdx.x % BLOCKS_PER_GROUP;
    const long long base = (long long)group * N_PER_GROUP + (long long)blk * ELEMS_PER_BLOCK;

    const float4* __restrict__ p4 = (const float4*)(p_in + base);
    const float4* __restrict__ t4 = (const float4*)(t_in + base);

    float sp = 0.f, st = 0.f, spt = 0.f;

    #pragma unroll
    for (int i = 0; i < VEC_PER_THREAD; i++) {
        const int idx = i * THREADS + threadIdx.x;
        float4 p = p4[idx];
        float4 t = t4[idx];
        sp  += p.x + p.y + p.z + p.w;
        st  += t.x + t.y + t.z + t.w;
        spt += p.x * t.x;
        spt += p.y * t.y;
        spt += p.z * t.z;
        spt += p.w * t.w;
    }

    // warp reduce
    #pragma unroll
    for (int off = 16; off > 0; off >>= 1) {
        sp  += __shfl_xor_sync(0xFFFFFFFFu, sp,  off);
        st  += __shfl_xor_sync(0xFFFFFFFFu, st,  off);
        spt += __shfl_xor_sync(0xFFFFFFFFu, spt, off);
    }

    __shared__ float s_sp[8], s_st[8], s_spt[8];
    const int wid = threadIdx.x >> 5;
    const int lid = threadIdx.x & 31;
    if (lid == 0) { s_sp[wid] = sp; s_st[wid] = st; s_spt[wid] = spt; }
    __syncthreads();

    if (wid == 0) {
        sp  = (lid < 8) ? s_sp[lid]  : 0.f;
        st  = (lid < 8) ? s_st[lid]  : 0.f;
        spt = (lid < 8) ? s_spt[lid] : 0.f;
        #pragma unroll
        for (int off = 4; off > 0; off >>= 1) {
            sp  += __shfl_xor_sync(0xFFFFFFFFu, sp,  off);
            st  += __shfl_xor_sync(0xFFFFFFFFu, st,  off);
            spt += __shfl_xor_sync(0xFFFFFFFFu, spt, off);
        }
        if (lid == 0) {
            float* dst = &g_partials[(group * BLOCKS_PER_GROUP + blk) * 4];
            dst[0] = sp; dst[1] = st; dst[2] = spt;
        }
    }
}

__global__ void cm_stage2(float* __restrict__ out) {
    // one block, GROUPS threads; each thread folds its group's 16 partials
    const int g = threadIdx.x;
    if (g >= GROUPS) return;
    float sp = 0.f, st = 0.f, spt = 0.f;
    #pragma unroll
    for (int b = 0; b < BLOCKS_PER_GROUP; b++) {
        const float* src = &g_partials[(g * BLOCKS_PER_GROUP + b) * 4];
        sp += src[0]; st += src[1]; spt += src[2];
    }
    const float Nf = (float)N_PER_GROUP;
    float* o = out + g * 4;
    o[0] = spt;                  // tp
    o[1] = Nf - sp - st + spt;   // tn
    o[2] = sp - spt;             // fp
    o[3] = st - spt;             // fn
}

extern "C" void kernel_launch(void* const* d_in, const int* in_sizes, int n_in,
                              void* d_out, int out_size) {
    const float* y_pred = (const float*)d_in[0];
    const float* y_true = (const float*)d_in[1];
    float* out = (float*)d_out;

    cm_stage1<<<GROUPS * BLOCKS_PER_GROUP, THREADS>>>(y_pred, y_true);
    cm_stage2<<<1, 64>>>(out);
}

// round 6
// speedup vs baseline: 1.0194x; 1.0194x over previous
#include <cuda_runtime.h>

// y_pred/y_true [16,3,512,512] f32 -> out [48,4].
// Per group g: sp=Σp, st=Σt, spt=Σpt; tp=spt, tn=N-sp-st+spt, fp=sp-spt, fn=st-spt.
// Single fused kernel: 16 blocks/group stream partials; last block per group
// (atomic counter) folds 16 partials deterministically and writes the 4 outputs,
// then resets the counter for the next graph replay.

constexpr int GROUPS = 48;
constexpr int N_PER_GROUP = 512 * 512;
constexpr int BLOCKS_PER_GROUP = 16;
constexpr int THREADS = 256;
constexpr int ELEMS_PER_BLOCK = N_PER_GROUP / BLOCKS_PER_GROUP;  // 16384
constexpr int VEC_PER_THREAD = ELEMS_PER_BLOCK / 4 / THREADS;    // 16

__device__ float g_partials[GROUPS * BLOCKS_PER_GROUP * 4];
__device__ unsigned int g_count[GROUPS];   // zero-init at module load; self-resetting

__global__ __launch_bounds__(THREADS, 8)
void cm_fused(const float* __restrict__ p_in, const float* __restrict__ t_in,
              float* __restrict__ out) {
    const int group = blockIdx.x / BLOCKS_PER_GROUP;
    const int blk   = blockIdx.x % BLOCKS_PER_GROUP;
    const long long base = (long long)group * N_PER_GROUP + (long long)blk * ELEMS_PER_BLOCK;

    const float4* __restrict__ p4 = (const float4*)(p_in + base);
    const float4* __restrict__ t4 = (const float4*)(t_in + base);

    float sp = 0.f, st = 0.f, spt = 0.f;

    #pragma unroll
    for (int i = 0; i < VEC_PER_THREAD; i++) {
        const int idx = i * THREADS + threadIdx.x;
        float4 p = p4[idx];
        float4 t = t4[idx];
        sp  += p.x + p.y + p.z + p.w;
        st  += t.x + t.y + t.z + t.w;
        spt += p.x * t.x;
        spt += p.y * t.y;
        spt += p.z * t.z;
        spt += p.w * t.w;
    }

    // intra-warp reduce
    #pragma unroll
    for (int off = 16; off > 0; off >>= 1) {
        sp  += __shfl_xor_sync(0xFFFFFFFFu, sp,  off);
        st  += __shfl_xor_sync(0xFFFFFFFFu, st,  off);
        spt += __shfl_xor_sync(0xFFFFFFFFu, spt, off);
    }

    __shared__ float s_sp[8], s_st[8], s_spt[8];
    __shared__ bool  s_last;
    const int wid = threadIdx.x >> 5;
    const int lid = threadIdx.x & 31;
    if (lid == 0) { s_sp[wid] = sp; s_st[wid] = st; s_spt[wid] = spt; }
    __syncthreads();

    if (threadIdx.x == 0) {
        float bsp = 0.f, bst = 0.f, bspt = 0.f;
        #pragma unroll
        for (int w = 0; w < 8; w++) { bsp += s_sp[w]; bst += s_st[w]; bspt += s_spt[w]; }
        float* dst = &g_partials[(group * BLOCKS_PER_GROUP + blk) * 4];
        dst[0] = bsp; dst[1] = bst; dst[2] = bspt;
        __threadfence();
        unsigned int prev = atomicAdd(&g_count[group], 1u);
        s_last = (prev == BLOCKS_PER_GROUP - 1);
    }
    __syncthreads();

    // last block of this group folds partials (fixed order -> deterministic)
    if (s_last && threadIdx.x == 0) {
        volatile float* parts = &g_partials[group * BLOCKS_PER_GROUP * 4];
        float fsp = 0.f, fst = 0.f, fspt = 0.f;
        #pragma unroll
        for (int b = 0; b < BLOCKS_PER_GROUP; b++) {
            fsp  += parts[b * 4 + 0];
            fst  += parts[b * 4 + 1];
            fspt += parts[b * 4 + 2];
        }
        const float Nf = (float)N_PER_GROUP;
        float* o = out + group * 4;
        o[0] = fspt;                    // tp
        o[1] = Nf - fsp - fst + fspt;   // tn
        o[2] = fsp - fspt;              // fp
        o[3] = fst - fspt;              // fn
        g_count[group] = 0;             // reset for next graph replay
        __threadfence();
    }
}

extern "C" void kernel_launch(void* const* d_in, const int* in_sizes, int n_in,
                              void* d_out, int out_size) {
    const float* y_pred = (const float*)d_in[0];
    const float* y_true = (const float*)d_in[1];
    float* out = (float*)d_out;
    cm_fused<<<GROUPS * BLOCKS_PER_GROUP, THREADS>>>(y_pred, y_true, out);
}